// round 3
// baseline (speedup 1.0000x reference)
#include <cuda_runtime.h>
#include <cuda_bf16.h>

// C[i, j] = A[i, i] * B[i, j]   with N = M = 8192, fp32.
// Pure streaming: read B, write C, gather diag(A) (negligible, warp-broadcast).
// float4 vectorized; row index via shift (2048 float4 per row).
// Grid is exact (16M vec / 256 = 65536 blocks) -> no tail guard needed.

static constexpr int N = 8192;
static constexpr int VEC_PER_ROW = N / 4;          // 2048
static constexpr int ROW_SHIFT = 11;               // log2(2048)

__global__ __launch_bounds__(256)
void diag_scale_kernel(const float* __restrict__ A,
                       const float4* __restrict__ B,
                       float4* __restrict__ C) {
    long long idx = (long long)blockIdx.x * blockDim.x + threadIdx.x;

    int row = (int)(idx >> ROW_SHIFT);
    // diag element: A[row * (N + 1)] — uniform per row, broadcast within warp
    float d = __ldg(&A[(long long)row * (N + 1)]);

    float4 b = B[idx];
    float4 c;
    c.x = d * b.x;
    c.y = d * b.y;
    c.z = d * b.z;
    c.w = d * b.w;
    C[idx] = c;
}

extern "C" void kernel_launch(void* const* d_in, const int* in_sizes, int n_in,
                              void* d_out, int out_size) {
    const float*  A = (const float*)d_in[0];
    const float4* B = (const float4*)d_in[1];
    float4*       C = (float4*)d_out;

    const int threads = 256;
    const int blocks = (N * VEC_PER_ROW) / threads;  // 65536, exact
    diag_scale_kernel<<<blocks, threads>>>(A, B, C);
}

// round 10
// speedup vs baseline: 1.0293x; 1.0293x over previous
#include <cuda_runtime.h>
#include <cuda_bf16.h>

// C[i, j] = A[i, i] * B[i, j]   with N = M = 8192, fp32.
// Streaming kernel at the HBM roofline. R3 measured 81us @ 76.6% DRAM with
// ILP=1. This version: each block owns 1024 contiguous float4 (half a row),
// each thread processes 4 float4 with front-batched loads (MLP_eff=4),
// diag value is block-uniform (row = blockIdx >> 1). Non-temporal ld/st
// since neither stream has reuse. (R4 harness timeout; R5-R9 broker
// timeouts — resubmitting unchanged, still never measured.)

static constexpr int N = 8192;
static constexpr int VEC_PER_ROW = N / 4;            // 2048
static constexpr int ILP = 4;
static constexpr int THREADS = 256;
static constexpr int VEC_PER_BLOCK = THREADS * ILP;  // 1024 = half a row

__global__ __launch_bounds__(THREADS)
void diag_scale_kernel(const float* __restrict__ A,
                       const float4* __restrict__ B,
                       float4* __restrict__ C) {
    // Each block: half of one row. Row index uniform across the block.
    int row = blockIdx.x >> 1;
    float d = __ldg(&A[(long long)row * (N + 1)]);

    long long base = (long long)blockIdx.x * VEC_PER_BLOCK + threadIdx.x;

    // Front-batch 4 independent 128-bit loads (MLP_eff = 4)
    float4 b0 = __ldcs(&B[base + 0 * THREADS]);
    float4 b1 = __ldcs(&B[base + 1 * THREADS]);
    float4 b2 = __ldcs(&B[base + 2 * THREADS]);
    float4 b3 = __ldcs(&B[base + 3 * THREADS]);

    float4 c0, c1, c2, c3;
    c0.x = d * b0.x; c0.y = d * b0.y; c0.z = d * b0.z; c0.w = d * b0.w;
    c1.x = d * b1.x; c1.y = d * b1.y; c1.z = d * b1.z; c1.w = d * b1.w;
    c2.x = d * b2.x; c2.y = d * b2.y; c2.z = d * b2.z; c2.w = d * b2.w;
    c3.x = d * b3.x; c3.y = d * b3.y; c3.z = d * b3.z; c3.w = d * b3.w;

    __stcs(&C[base + 0 * THREADS], c0);
    __stcs(&C[base + 1 * THREADS], c1);
    __stcs(&C[base + 2 * THREADS], c2);
    __stcs(&C[base + 3 * THREADS], c3);
}

extern "C" void kernel_launch(void* const* d_in, const int* in_sizes, int n_in,
                              void* d_out, int out_size) {
    const float*  A = (const float*)d_in[0];
    const float4* B = (const float4*)d_in[1];
    float4*       C = (float4*)d_out;

    const int blocks = (N * VEC_PER_ROW) / VEC_PER_BLOCK;  // 16384, exact
    diag_scale_kernel<<<blocks, THREADS>>>(A, B, C);
}

// round 11
// speedup vs baseline: 1.0305x; 1.0012x over previous
#include <cuda_runtime.h>
#include <cuda_bf16.h>

// C[i, j] = A[i, i] * B[i, j]   with N = M = 8192, fp32.
// R10 (ILP=4, .cs): kernel 75.0us @ 81.1% DRAM / 6427 GB/s. This version:
// ILP=8 — each block owns exactly ONE row (256 thr x 8 float4 = 2048 vec),
// row = blockIdx.x, 8 front-batched 128-bit loads per thread (MLP_eff=8).
// Non-temporal .cs both directions (zero-reuse streams).

static constexpr int N = 8192;
static constexpr int VEC_PER_ROW = N / 4;            // 2048
static constexpr int ILP = 8;
static constexpr int THREADS = 256;
static constexpr int VEC_PER_BLOCK = THREADS * ILP;  // 2048 = one full row

__global__ __launch_bounds__(THREADS)
void diag_scale_kernel(const float* __restrict__ A,
                       const float4* __restrict__ B,
                       float4* __restrict__ C) {
    // One row per block: diag value uniform across the whole block.
    int row = blockIdx.x;
    float d = __ldg(&A[(long long)row * (N + 1)]);

    long long base = (long long)row * VEC_PER_ROW + threadIdx.x;

    // Front-batch 8 independent 128-bit loads (MLP_eff = 8)
    float4 b0 = __ldcs(&B[base + 0 * THREADS]);
    float4 b1 = __ldcs(&B[base + 1 * THREADS]);
    float4 b2 = __ldcs(&B[base + 2 * THREADS]);
    float4 b3 = __ldcs(&B[base + 3 * THREADS]);
    float4 b4 = __ldcs(&B[base + 4 * THREADS]);
    float4 b5 = __ldcs(&B[base + 5 * THREADS]);
    float4 b6 = __ldcs(&B[base + 6 * THREADS]);
    float4 b7 = __ldcs(&B[base + 7 * THREADS]);

    float4 c0, c1, c2, c3, c4, c5, c6, c7;
    c0.x = d * b0.x; c0.y = d * b0.y; c0.z = d * b0.z; c0.w = d * b0.w;
    c1.x = d * b1.x; c1.y = d * b1.y; c1.z = d * b1.z; c1.w = d * b1.w;
    c2.x = d * b2.x; c2.y = d * b2.y; c2.z = d * b2.z; c2.w = d * b2.w;
    c3.x = d * b3.x; c3.y = d * b3.y; c3.z = d * b3.z; c3.w = d * b3.w;
    c4.x = d * b4.x; c4.y = d * b4.y; c4.z = d * b4.z; c4.w = d * b4.w;
    c5.x = d * b5.x; c5.y = d * b5.y; c5.z = d * b5.z; c5.w = d * b5.w;
    c6.x = d * b6.x; c6.y = d * b6.y; c6.z = d * b6.z; c6.w = d * b6.w;
    c7.x = d * b7.x; c7.y = d * b7.y; c7.z = d * b7.z; c7.w = d * b7.w;

    __stcs(&C[base + 0 * THREADS], c0);
    __stcs(&C[base + 1 * THREADS], c1);
    __stcs(&C[base + 2 * THREADS], c2);
    __stcs(&C[base + 3 * THREADS], c3);
    __stcs(&C[base + 4 * THREADS], c4);
    __stcs(&C[base + 5 * THREADS], c5);
    __stcs(&C[base + 6 * THREADS], c6);
    __stcs(&C[base + 7 * THREADS], c7);
}

extern "C" void kernel_launch(void* const* d_in, const int* in_sizes, int n_in,
                              void* d_out, int out_size) {
    const float*  A = (const float*)d_in[0];
    const float4* B = (const float4*)d_in[1];
    float4*       C = (float4*)d_out;

    const int blocks = N;  // one row per block, 8192 blocks, exact
    diag_scale_kernel<<<blocks, THREADS>>>(A, B, C);
}